// round 10
// baseline (speedup 1.0000x reference)
#include <cuda_runtime.h>

// STTEncoder: replicate the reference's fp32 integral image bitwise.
// jnp.cumsum -> reduce_window -> XLA ReduceWindowRewriter(base=16):
// blocked-sequential recursive scan (PASS since R7, rel_err 1.6e-8).
// R10: stage1 all-vector smem (STS.128/LDS.128 conflict-free layout);
// stage2 parallelized across y-blocks (2a folds, 2b combine), final
// offset-add fused into stage3 (same rounding tree op-for-op).

#define IMG_W 1280
#define TS 16
constexpr int NTOK = 172;
constexpr int N1 = IMG_W + 1;   // padded scan length (1281)
constexpr int NB1 = 81;         // ceil(1281/16)
constexpr int NB1P = 96;        // padded to 6*16
constexpr int NB2 = 6;

struct Tok { int x, y, s; };
struct Table { Tok t[NTOK]; int count; };

constexpr Table make_table() {
    Table tb{};
    constexpr int STR[5] = {1, 2, 4, 6, 8};
    constexpr int GRD[5] = {4, 4, 6, 8, 10};
    int n = 0;
    int plo = 0, phi = 0;
    bool has = false;
    for (int sc = 0; sc < 5; ++sc) {
        int s = STR[sc], g = GRD[sc];
        int cov = g * TS * s;
        int off = (IMG_W - cov) / 2;
        for (int j = 0; j < g; ++j)
            for (int i = 0; i < g; ++i) {
                int x = off + i * TS * s;
                int y = off + j * TS * s;
                if (has && x >= plo && x + TS * s <= phi &&
                    y >= plo && y + TS * s <= phi)
                    continue;
                tb.t[n].x = x; tb.t[n].y = y; tb.t[n].s = s; ++n;
            }
        plo = off; phi = off + cov; has = true;
    }
    tb.count = n;
    return tb;
}
static_assert(make_table().count == NTOK, "token count mismatch");
__constant__ Table TOKS = make_table();

// ---- needed boundary coordinate set (same for x and y) ----
struct BMask { bool m[N1]; };
constexpr BMask make_bmask() {
    BMask b{};
    Table tb = make_table();
    for (int t = 0; t < NTOK; ++t) {
        int s = tb.t[t].s;
        for (int i = 0; i <= TS; ++i) {
            b.m[tb.t[t].x + s * i] = true;
            b.m[tb.t[t].y + s * i] = true;
        }
    }
    return b;
}
constexpr int count_bounds() {
    BMask b = make_bmask(); int c = 0;
    for (int i = 0; i < N1; ++i) if (b.m[i]) ++c;
    return c;
}
constexpr int NX = count_bounds();
static_assert(NX <= 512, "boundary set too large");
constexpr int NX32 = (NX + 31) / 32 * 32;
constexpr int NCG = NX32 / 32;              // column groups

struct BMapT { short cmap[N1]; };
constexpr BMapT make_bmap() {
    BMapT r{};
    BMask b = make_bmask();
    int c = 0;
    for (int i = 0; i < N1; ++i) {
        if (b.m[i]) { r.cmap[i] = (short)c; ++c; }
        else r.cmap[i] = -1;
    }
    return r;
}
__device__ const BMapT BMAP = make_bmap();

// per-16-block needed-position mask + cumulative output base
struct BlkInfo { unsigned short mask; short base; };
struct BlkTab { BlkInfo b[NB1]; int total; };
constexpr BlkTab make_blk() {
    BlkTab t{};
    BMask m = make_bmask();
    int cnt = 0;
    for (int r = 0; r < NB1; ++r) {
        t.b[r].base = (short)cnt;
        unsigned short msk = 0;
        for (int j = 0; j < 16; ++j) {
            int i = r * 16 + j;
            if (i < N1 && m.m[i]) { msk |= (unsigned short)(1u << j); ++cnt; }
        }
        t.b[r].mask = msk;
    }
    t.total = cnt;
    return t;
}
static_assert(make_blk().total == NX, "mask/base table inconsistent");
__device__ const BlkTab BLK = make_blk();

// block index (coord>>4) of each sampled coordinate
struct RTab { short r[NX]; };
constexpr RTab make_rtab() {
    RTab t{};
    BMask b = make_bmask();
    int c = 0;
    for (int i = 0; i < N1; ++i)
        if (b.m[i]) { t.r[c] = (short)(i >> 4); ++c; }
    return t;
}
__device__ const RTab RBLK = make_rtab();

// ---- scratch (device globals: no allocation allowed) ----
__device__ float g_Sx[48ull * IMG_W * NX32];     // [bc][y][xc]
__device__ float g_P[48ull * NX * NX32];         // sampled level-1 y-prefixes
__device__ float g_B[48ull * NB1 * NX32];        // y block sums
__device__ float g_Add[48ull * NB1 * NX32];      // add[r][col] = off2+b2prefix

// ======================= Stage 1: x-scan per image row =======================
// smem layout: float4 j at word 4j+4*(j>>3)  (16B pad every 8 float4s).
// STS.128 conflict-free; block r's 4 float4s contiguous at W(r)=16r+4*(r>>1),
// LDS.128 phase start banks {0,16,4,20,8,24,12,28} -> conflict-free.
__global__ __launch_bounds__(128) void stt_stage1(const float* __restrict__ img) {
    __shared__ __align__(16) float srow[4 * 320 + 4 * 40];   // 1440 words
    __shared__ float s_bsum[NB1P];
    __shared__ float s_off2[NB2];
    __shared__ float s_out[NX];
    const int y  = blockIdx.x;
    const int bc = blockIdx.y;
    const int t  = threadIdx.x;       // 0..127

    const float4* src4 = reinterpret_cast<const float4*>(
        img + ((size_t)bc * IMG_W + y) * IMG_W);
#pragma unroll
    for (int k = 0; k < 3; ++k) {
        const int j = t + k * 128;
        if (j < 320)
            *reinterpret_cast<float4*>(&srow[4 * j + 4 * (j >> 3)]) = src4[j];
    }
    __syncthreads();

    // level 1: sequential fold of padded block r = elements [16r,16r+16)
    float p[16];
    if (t < NB1) {
        const int r = t;
        float e0 = 0.f;
        if (r > 0) {                      // pixel 16r-1 = float4 4r-1, elem 3
            const int jj = 4 * r - 1;
            e0 = srow[4 * jj + 4 * (jj >> 3) + 3];
        }
        float acc = 0.f + e0;
        p[0] = acc;
        if (r < 80) {
            const int W = 16 * r + 4 * (r >> 1);
            const float4 a = *reinterpret_cast<const float4*>(&srow[W]);
            const float4 b = *reinterpret_cast<const float4*>(&srow[W + 4]);
            const float4 c = *reinterpret_cast<const float4*>(&srow[W + 8]);
            const float4 d = *reinterpret_cast<const float4*>(&srow[W + 12]);
            acc = acc + a.x; p[1]  = acc;
            acc = acc + a.y; p[2]  = acc;
            acc = acc + a.z; p[3]  = acc;
            acc = acc + a.w; p[4]  = acc;
            acc = acc + b.x; p[5]  = acc;
            acc = acc + b.y; p[6]  = acc;
            acc = acc + b.z; p[7]  = acc;
            acc = acc + b.w; p[8]  = acc;
            acc = acc + c.x; p[9]  = acc;
            acc = acc + c.y; p[10] = acc;
            acc = acc + c.z; p[11] = acc;
            acc = acc + c.w; p[12] = acc;
            acc = acc + d.x; p[13] = acc;
            acc = acc + d.y; p[14] = acc;
            acc = acc + d.z; p[15] = acc;
        }
        s_bsum[r] = acc;
    } else if (t < NB1P) {
        s_bsum[t] = 0.f;
    }
    __syncthreads();

    // level 2: sequential prefix within 16-groups of block sums (in place)
    if (t < NB2) {
        const int base = t * 16;
        float acc = 0.f;
#pragma unroll
        for (int u = 0; u < 16; ++u) { acc = acc + s_bsum[base + u]; s_bsum[base + u] = acc; }
    }
    __syncthreads();

    // level 3: exclusive fold of group totals
    if (t == 0) {
        float acc = 0.f;
        s_off2[0] = 0.f;
#pragma unroll
        for (int u = 0; u < NB2 - 1; ++u) { acc = acc + s_bsum[u * 16 + 15]; s_off2[u + 1] = acc; }
    }
    __syncthreads();

    // sampled values, compacted: S[i] = (off2 + b2prefix) + P
    if (t < NB1) {
        const int r = t;
        const BlkInfo bi = BLK.b[r];
        if (bi.mask) {
            float add = 0.f;
            if (r > 0) add = s_off2[(r - 1) >> 4] + s_bsum[r - 1];
            int o = bi.base;
#pragma unroll
            for (int j = 0; j < 16; ++j)
                if ((bi.mask >> j) & 1) { s_out[o] = r ? (add + p[j]) : p[j]; ++o; }
        }
    }
    __syncthreads();

    float* dst = g_Sx + ((size_t)bc * IMG_W + y) * NX32;
    for (int i = t; i < NX; i += 128) dst[i] = s_out[i];    // coalesced
}

// ========= Stage 2a: y level-1 folds, parallel over (y-block, col) ==========
__global__ __launch_bounds__(128) void stt_stage2a() {
    const int warp = threadIdx.x >> 5, lane = threadIdx.x & 31;
    const int r  = blockIdx.y * 4 + warp;
    if (r >= NB1) return;
    const int bc = blockIdx.z;
    const int col = blockIdx.x * 32 + lane;

    const float* src = g_Sx + (size_t)bc * IMG_W * NX32 + col;
    float e[16];
#pragma unroll
    for (int j = 0; j < 16; ++j) {        // 16 independent coalesced loads
        const int yy = r * 16 + j - 1;    // padded elem 16r+j = row (16r+j-1)
        e[j] = (yy >= 0 && yy < IMG_W) ? src[(size_t)yy * NX32] : 0.f;
    }

    const BlkInfo bi = BLK.b[r];
    float* P = g_P + (size_t)bc * NX * NX32 + col;
    float acc = 0.f;
    int o = bi.base;
#pragma unroll
    for (int j = 0; j < 16; ++j) {
        acc = acc + e[j];                 // exact fold order (== R9 tile loop)
        if ((bi.mask >> j) & 1) { P[(size_t)o * NX32] = acc; ++o; }
    }
    g_B[((size_t)bc * NB1 + r) * NX32 + col] = acc;
}

// ===== Stage 2b: exact level-2/3 combine over block sums (per column) =======
__global__ __launch_bounds__(32) void stt_stage2b() {
    const int col = blockIdx.x * 32 + threadIdx.x;
    const int bc  = blockIdx.y;
    const float* B = g_B   + (size_t)bc * NB1 * NX32 + col;
    float*       A = g_Add + (size_t)bc * NB1 * NX32 + col;

    float acc2 = 0.f;     // b2prefix[r-1] at block entry
    float off_cur = 0.f;  // off2[current group]
#pragma unroll 4
    for (int r = 0; r < NB1; ++r) {
        const float Bv = B[(size_t)r * NX32];
        const float off_used = off_cur;
        if (r > 0 && (r & 15) == 0)
            off_cur = off_cur + acc2;            // off2[u] = off2[u-1]+total[u-1]
        A[(size_t)r * NX32] = off_used + acc2;   // add[r] (r=0 slot unused)
        acc2 = ((r & 15) == 0) ? Bv : (acc2 + Bv);
    }
}

// ====== Stage 3: fused final offset-add + 4-corner gather + divide ==========
__global__ __launch_bounds__(256) void stt_stage3(float* __restrict__ out) {
    const int tok = blockIdx.x;
    const int bc  = blockIdx.y;
    const Tok t = TOKS.t[tok];
    const int tx = threadIdx.x, ty = threadIdx.y;

    const int xl = t.x + t.s * tx, xu = xl + t.s;
    const int yl = t.y + t.s * ty, yu = yl + t.s;
    const int cxl = BMAP.cmap[xl], cxu = BMAP.cmap[xu];
    const int cyl = BMAP.cmap[yl], cyu = BMAP.cmap[yu];

    const float* P   = g_P   + (size_t)bc * NX * NX32;
    const float* Add = g_Add + (size_t)bc * NB1 * NX32;

    // ii(yc,xc) = r==0 ? p : add[r] + p   (single rounded add, exact order)
    auto iival = [&](int yc, int xc) -> float {
        float v = P[(size_t)yc * NX32 + xc];
        const int r = RBLK.r[yc];
        if (r > 0) v = Add[(size_t)r * NX32 + xc] + v;
        return v;
    };

    const float A = iival(cyu, cxu);
    const float B = iival(cyu, cxl);
    const float C = iival(cyl, cxu);
    const float D = iival(cyl, cxl);
    const float box = ((A - B) - C) + D;   // reference op order

    const int b = bc / 3, ch = bc % 3;
    const size_t o = ((((size_t)b * NTOK + tok) * 3 + ch) * TS + ty) * TS + tx;
    out[o] = box / (float)(t.s * t.s);
}

extern "C" void kernel_launch(void* const* d_in, const int* in_sizes, int n_in,
                              void* d_out, int out_size) {
    const float* img = (const float*)d_in[0];
    float* out = (float*)d_out;

    dim3 g1(IMG_W, 48);
    stt_stage1<<<g1, 128>>>(img);

    dim3 g2a(NCG, (NB1 + 3) / 4, 48);
    stt_stage2a<<<g2a, 128>>>();

    dim3 g2b(NCG, 48);
    stt_stage2b<<<g2b, 32>>>();

    dim3 g3(NTOK, 48);
    stt_stage3<<<g3, dim3(TS, TS)>>>(out);
}

// round 11
// speedup vs baseline: 1.0200x; 1.0200x over previous
#include <cuda_runtime.h>

// STTEncoder: replicate the reference's fp32 integral image bitwise.
// jnp.cumsum -> reduce_window -> XLA ReduceWindowRewriter(base=16):
// blocked-sequential recursive scan (PASS since R7, rel_err 1.6e-8).
// R11: stage1 rewritten to kill the runtime-mask sample scatter (now a
// constexpr-table gather with coalesced STG) and the level-2 smem chain
// (now register folds). All rounding orders preserved op-for-op.

#define IMG_W 1280
#define TS 16
constexpr int NTOK = 172;
constexpr int N1 = IMG_W + 1;   // padded scan length (1281)
constexpr int NB1 = 81;         // ceil(1281/16)
constexpr int NB1P = 96;        // padded to 6*16
constexpr int NB2 = 6;

struct Tok { int x, y, s; };
struct Table { Tok t[NTOK]; int count; };

constexpr Table make_table() {
    Table tb{};
    constexpr int STR[5] = {1, 2, 4, 6, 8};
    constexpr int GRD[5] = {4, 4, 6, 8, 10};
    int n = 0;
    int plo = 0, phi = 0;
    bool has = false;
    for (int sc = 0; sc < 5; ++sc) {
        int s = STR[sc], g = GRD[sc];
        int cov = g * TS * s;
        int off = (IMG_W - cov) / 2;
        for (int j = 0; j < g; ++j)
            for (int i = 0; i < g; ++i) {
                int x = off + i * TS * s;
                int y = off + j * TS * s;
                if (has && x >= plo && x + TS * s <= phi &&
                    y >= plo && y + TS * s <= phi)
                    continue;
                tb.t[n].x = x; tb.t[n].y = y; tb.t[n].s = s; ++n;
            }
        plo = off; phi = off + cov; has = true;
    }
    tb.count = n;
    return tb;
}
static_assert(make_table().count == NTOK, "token count mismatch");
__constant__ Table TOKS = make_table();

// ---- needed boundary coordinate set (same for x and y) ----
struct BMask { bool m[N1]; };
constexpr BMask make_bmask() {
    BMask b{};
    Table tb = make_table();
    for (int t = 0; t < NTOK; ++t) {
        int s = tb.t[t].s;
        for (int i = 0; i <= TS; ++i) {
            b.m[tb.t[t].x + s * i] = true;
            b.m[tb.t[t].y + s * i] = true;
        }
    }
    return b;
}
constexpr int count_bounds() {
    BMask b = make_bmask(); int c = 0;
    for (int i = 0; i < N1; ++i) if (b.m[i]) ++c;
    return c;
}
constexpr int NX = count_bounds();
static_assert(NX <= 512, "boundary set too large");
constexpr int NX32 = (NX + 31) / 32 * 32;
constexpr int NCG = NX32 / 32;              // column groups

struct BMapT { short cmap[N1]; };
constexpr BMapT make_bmap() {
    BMapT r{};
    BMask b = make_bmask();
    int c = 0;
    for (int i = 0; i < N1; ++i) {
        if (b.m[i]) { r.cmap[i] = (short)c; ++c; }
        else r.cmap[i] = -1;
    }
    return r;
}
__device__ const BMapT BMAP = make_bmap();

// per-16-block needed-position mask + cumulative output base (stage 2a)
struct BlkInfo { unsigned short mask; short base; };
struct BlkTab { BlkInfo b[NB1]; int total; };
constexpr BlkTab make_blk() {
    BlkTab t{};
    BMask m = make_bmask();
    int cnt = 0;
    for (int r = 0; r < NB1; ++r) {
        t.b[r].base = (short)cnt;
        unsigned short msk = 0;
        for (int j = 0; j < 16; ++j) {
            int i = r * 16 + j;
            if (i < N1 && m.m[i]) { msk |= (unsigned short)(1u << j); ++cnt; }
        }
        t.b[r].mask = msk;
    }
    t.total = cnt;
    return t;
}
static_assert(make_blk().total == NX, "mask/base table inconsistent");
__device__ const BlkTab BLK = make_blk();

// block index (coord>>4) of each sampled coordinate (stage 3)
struct RTab { short r[NX]; };
constexpr RTab make_rtab() {
    RTab t{};
    BMask b = make_bmask();
    int c = 0;
    for (int i = 0; i < N1; ++i)
        if (b.m[i]) { t.r[c] = (short)(i >> 4); ++c; }
    return t;
}
__device__ const RTab RBLK = make_rtab();

// stage1 sample table: pfx word index | (block r << 16), in cmap order
constexpr int PFXW = 1456;   // W(80)=1440, +16 for the (partly unused) last store
struct STab { int v[NX]; };
constexpr STab make_stab() {
    STab t{};
    BMask b = make_bmask();
    int c = 0;
    for (int i = 0; i < N1; ++i)
        if (b.m[i]) {
            const int r = i >> 4, j = i & 15;
            const int w = 16 * r + 4 * (r >> 1) + j;
            t.v[c] = w | (r << 16);
            ++c;
        }
    return t;
}
__device__ const STab SPOS = make_stab();

// ---- scratch (device globals: no allocation allowed) ----
__device__ float g_Sx[48ull * IMG_W * NX32];     // [bc][y][xc]
__device__ float g_P[48ull * NX * NX32];         // sampled level-1 y-prefixes
__device__ float g_B[48ull * NB1 * NX32];        // y block sums
__device__ float g_Add[48ull * NB1 * NX32];      // add[r][col] = off2+b2prefix

// ======================= Stage 1: x-scan per image row =======================
// srow/pfx layout: float4 j at word 4j+4*(j>>3); block r's 16 words contiguous
// at W(r)=16r+4*(r>>1). STS.128/LDS.128 both bank-conflict-free.
__global__ __launch_bounds__(128) void stt_stage1(const float* __restrict__ img) {
    __shared__ __align__(16) float srow[1440];
    __shared__ __align__(16) float pfx[PFXW];
    __shared__ __align__(16) float s_bsum[NB1P];
    __shared__ float s_off2[NB2];
    __shared__ float s_add[NB1];
    const int y  = blockIdx.x;
    const int bc = blockIdx.y;
    const int t  = threadIdx.x;       // 0..127

    const float4* src4 = reinterpret_cast<const float4*>(
        img + ((size_t)bc * IMG_W + y) * IMG_W);
#pragma unroll
    for (int k = 0; k < 3; ++k) {
        const int j = t + k * 128;
        if (j < 320)
            *reinterpret_cast<float4*>(&srow[4 * j + 4 * (j >> 3)]) = src4[j];
    }
    __syncthreads();

    // level 1: sequential fold of padded block r; prefixes -> pfx (vector STS)
    if (t < NB1) {
        const int r = t;
        float e0 = 0.f;
        if (r > 0) {                      // pixel 16r-1 = float4 4r-1, elem 3
            const int jj = 4 * r - 1;
            e0 = srow[4 * jj + 4 * (jj >> 3) + 3];
        }
        float acc = 0.f + e0;             // exact: fold init 0 + first element
        float4 P0 = make_float4(acc, 0.f, 0.f, 0.f);
        float4 P1 = P0, P2 = P0, P3 = P0;
        const int W = 16 * r + 4 * (r >> 1);
        if (r < 80) {
            const float4 a = *reinterpret_cast<const float4*>(&srow[W]);
            const float4 b = *reinterpret_cast<const float4*>(&srow[W + 4]);
            const float4 c = *reinterpret_cast<const float4*>(&srow[W + 8]);
            const float4 d = *reinterpret_cast<const float4*>(&srow[W + 12]);
            acc = acc + a.x; P0.y = acc;
            acc = acc + a.y; P0.z = acc;
            acc = acc + a.z; P0.w = acc;
            acc = acc + a.w; P1.x = acc;
            acc = acc + b.x; P1.y = acc;
            acc = acc + b.y; P1.z = acc;
            acc = acc + b.z; P1.w = acc;
            acc = acc + b.w; P2.x = acc;
            acc = acc + c.x; P2.y = acc;
            acc = acc + c.y; P2.z = acc;
            acc = acc + c.z; P2.w = acc;
            acc = acc + c.w; P3.x = acc;
            acc = acc + d.x; P3.y = acc;
            acc = acc + d.y; P3.z = acc;
            acc = acc + d.z; P3.w = acc;
        }
        *reinterpret_cast<float4*>(&pfx[W])      = P0;
        *reinterpret_cast<float4*>(&pfx[W + 4])  = P1;
        *reinterpret_cast<float4*>(&pfx[W + 8])  = P2;
        *reinterpret_cast<float4*>(&pfx[W + 12]) = P3;
        s_bsum[r] = acc;
    } else if (t < NB1P) {
        s_bsum[t] = 0.f;                  // padded block sums
    }
    __syncthreads();

    // level 2: register fold of 16 block sums per group (in-place, same order)
    if (t < NB2) {
        float* bs = &s_bsum[t * 16];
        float4 a = *reinterpret_cast<const float4*>(bs);
        float4 b = *reinterpret_cast<const float4*>(bs + 4);
        float4 c = *reinterpret_cast<const float4*>(bs + 8);
        float4 d = *reinterpret_cast<const float4*>(bs + 12);
        float acc = 0.f;
        acc = acc + a.x; a.x = acc;
        acc = acc + a.y; a.y = acc;
        acc = acc + a.z; a.z = acc;
        acc = acc + a.w; a.w = acc;
        acc = acc + b.x; b.x = acc;
        acc = acc + b.y; b.y = acc;
        acc = acc + b.z; b.z = acc;
        acc = acc + b.w; b.w = acc;
        acc = acc + c.x; c.x = acc;
        acc = acc + c.y; c.y = acc;
        acc = acc + c.z; c.z = acc;
        acc = acc + c.w; c.w = acc;
        acc = acc + d.x; d.x = acc;
        acc = acc + d.y; d.y = acc;
        acc = acc + d.z; d.z = acc;
        acc = acc + d.w; d.w = acc;
        *reinterpret_cast<float4*>(bs)      = a;
        *reinterpret_cast<float4*>(bs + 4)  = b;
        *reinterpret_cast<float4*>(bs + 8)  = c;
        *reinterpret_cast<float4*>(bs + 12) = d;
    }
    __syncthreads();

    // level 3: exclusive fold of group totals
    if (t == 0) {
        float acc = 0.f;
        s_off2[0] = 0.f;
#pragma unroll
        for (int u = 0; u < NB2 - 1; ++u) { acc = acc + s_bsum[u * 16 + 15]; s_off2[u + 1] = acc; }
    }
    __syncthreads();

    // add[r] = off2[(r-1)>>4] + b2prefix[r-1]   (r>=1)
    if (t < NB1)
        s_add[t] = (t == 0) ? 0.f : (s_off2[(t - 1) >> 4] + s_bsum[t - 1]);
    __syncthreads();

    // table-driven sample gather, coalesced STG: S = r ? add[r]+p : p
    float* dst = g_Sx + ((size_t)bc * IMG_W + y) * NX32;
#pragma unroll
    for (int k = 0; k < 3; ++k) {
        const int i = t + k * 128;
        if (i < NX) {
            const int pk = SPOS.v[i];
            const int w = pk & 0xFFFF, r = pk >> 16;
            const float p = pfx[w];
            dst[i] = r ? (s_add[r] + p) : p;
        }
    }
}

// ========= Stage 2a: y level-1 folds, parallel over (y-block, col) ==========
__global__ __launch_bounds__(128) void stt_stage2a() {
    const int warp = threadIdx.x >> 5, lane = threadIdx.x & 31;
    const int r  = blockIdx.y * 4 + warp;
    if (r >= NB1) return;
    const int bc = blockIdx.z;
    const int col = blockIdx.x * 32 + lane;

    const float* src = g_Sx + (size_t)bc * IMG_W * NX32 + col;
    float e[16];
#pragma unroll
    for (int j = 0; j < 16; ++j) {        // 16 independent coalesced loads
        const int yy = r * 16 + j - 1;    // padded elem 16r+j = row (16r+j-1)
        e[j] = (yy >= 0 && yy < IMG_W) ? src[(size_t)yy * NX32] : 0.f;
    }

    const BlkInfo bi = BLK.b[r];
    float* P = g_P + (size_t)bc * NX * NX32 + col;
    float acc = 0.f;
    int o = bi.base;
#pragma unroll
    for (int j = 0; j < 16; ++j) {
        acc = acc + e[j];                 // exact fold order
        if ((bi.mask >> j) & 1) { P[(size_t)o * NX32] = acc; ++o; }
    }
    g_B[((size_t)bc * NB1 + r) * NX32 + col] = acc;
}

// ===== Stage 2b: exact level-2/3 combine over block sums (per column) =======
__global__ __launch_bounds__(32) void stt_stage2b() {
    const int col = blockIdx.x * 32 + threadIdx.x;
    const int bc  = blockIdx.y;
    const float* B = g_B   + (size_t)bc * NB1 * NX32 + col;
    float*       A = g_Add + (size_t)bc * NB1 * NX32 + col;

    float acc2 = 0.f;     // b2prefix[r-1] at block entry
    float off_cur = 0.f;  // off2[current group]
#pragma unroll 4
    for (int r = 0; r < NB1; ++r) {
        const float Bv = B[(size_t)r * NX32];
        const float off_used = off_cur;
        if (r > 0 && (r & 15) == 0)
            off_cur = off_cur + acc2;            // off2[u] = off2[u-1]+total[u-1]
        A[(size_t)r * NX32] = off_used + acc2;   // add[r] (r=0 slot unused)
        acc2 = ((r & 15) == 0) ? Bv : (acc2 + Bv);
    }
}

// ====== Stage 3: fused final offset-add + 4-corner gather + divide ==========
__global__ __launch_bounds__(256) void stt_stage3(float* __restrict__ out) {
    const int tok = blockIdx.x;
    const int bc  = blockIdx.y;
    const Tok t = TOKS.t[tok];
    const int tx = threadIdx.x, ty = threadIdx.y;

    const int xl = t.x + t.s * tx, xu = xl + t.s;
    const int yl = t.y + t.s * ty, yu = yl + t.s;
    const int cxl = BMAP.cmap[xl], cxu = BMAP.cmap[xu];
    const int cyl = BMAP.cmap[yl], cyu = BMAP.cmap[yu];

    const float* P   = g_P   + (size_t)bc * NX * NX32;
    const float* Add = g_Add + (size_t)bc * NB1 * NX32;

    // ii(yc,xc) = r==0 ? p : add[r] + p   (single rounded add, exact order)
    auto iival = [&](int yc, int xc) -> float {
        float v = P[(size_t)yc * NX32 + xc];
        const int r = RBLK.r[yc];
        if (r > 0) v = Add[(size_t)r * NX32 + xc] + v;
        return v;
    };

    const float A = iival(cyu, cxu);
    const float B = iival(cyu, cxl);
    const float C = iival(cyl, cxu);
    const float D = iival(cyl, cxl);
    const float box = ((A - B) - C) + D;   // reference op order

    const int b = bc / 3, ch = bc % 3;
    const size_t o = ((((size_t)b * NTOK + tok) * 3 + ch) * TS + ty) * TS + tx;
    out[o] = box / (float)(t.s * t.s);
}

extern "C" void kernel_launch(void* const* d_in, const int* in_sizes, int n_in,
                              void* d_out, int out_size) {
    const float* img = (const float*)d_in[0];
    float* out = (float*)d_out;

    dim3 g1(IMG_W, 48);
    stt_stage1<<<g1, 128>>>(img);

    dim3 g2a(NCG, (NB1 + 3) / 4, 48);
    stt_stage2a<<<g2a, 128>>>();

    dim3 g2b(NCG, 48);
    stt_stage2b<<<g2b, 32>>>();

    dim3 g3(NTOK, 48);
    stt_stage3<<<g3, dim3(TS, TS)>>>(out);
}